// round 5
// baseline (speedup 1.0000x reference)
#include <cuda_runtime.h>
#include <cstdint>

#define N_PRED   25200
#define N_S      19200
#define N_SM     24000   // s + m
#define TOPK     4096
#define NBIN     8192
#define CAND_CAP 8192
#define NWORD    128     // TOPK / 32

// ---------------- scratch (static __device__, no allocations) ----------------
__device__ float              g_score[N_PRED];
__device__ int                g_cls[N_PRED];
__device__ float4             g_box[N_PRED];
__device__ unsigned           g_hist[NBIN];
__device__ int                g_cnt;
__device__ int                g_binThresh;
__device__ unsigned long long g_cand[CAND_CAP];
__device__ float4             g_topbox[TOPK];
__device__ int                g_topcls[TOPK];
__device__ unsigned           g_validw[NWORD];
__device__ unsigned           g_mask[TOPK * NWORD];   // 2 MB suppression bitmask

__device__ __forceinline__ unsigned ord32(float f) {
    unsigned u = __float_as_uint(f);
    return (u & 0x80000000u) ? ~u : (u | 0x80000000u);
}

// ---------------- K0: clear counters ----------------
__global__ void k_init() {
    int t = blockIdx.x * blockDim.x + threadIdx.x;
    if (t < NBIN) g_hist[t] = 0u;
    if (t == 0)   g_cnt = 0;
}

// ---------------- K1: decode all predictions ----------------
// Score replicates XLA:GPU fused softmax bit-for-bit (hypothesis):
//   mx   = max(x)                          (order-independent)
//   e_c  = __nv_expf(x_c - mx)             (expf == XLA's exp lowering)
//   sum  = warp-shuffle-tree reduction:    (w0 + w2) + w1, each w a
//          halving shfl.down tree (16,8,4,2,1) over 32 (w2: 16 + pad0)
//   s_c  = sig * (e_c / sum)               (IEEE div + mul per class)
//   sc   = max_c s_c, am = first argmax    (strict > scan)
__global__ void k_decode(const float* __restrict__ ps, const float* __restrict__ pm,
                         const float* __restrict__ pl, const float* __restrict__ anch) {
    int idx = blockIdx.x * blockDim.x + threadIdx.x;
    if (idx >= N_PRED) return;

    const float* p; int HW, W, lvl, li; float stride;
    if (idx < N_S)       { p = ps; HW = 6400; W = 80; stride = 8.f;  lvl = 0; li = idx; }
    else if (idx < N_SM) { p = pm; HW = 1600; W = 40; stride = 16.f; lvl = 1; li = idx - N_S; }
    else                 { p = pl; HW = 400;  W = 20; stride = 32.f; lvl = 2; li = idx - N_SM; }

    int pos = li / 3, a = li - pos * 3;
    int hh = pos / W, ww = pos - hh * W;
    const float* q = p + pos;

    float obj = __ldg(q + a * HW);

    // ---- pass 1: row max (order-independent) ----
    int cb = 3 + a * 80;
    float mx = -3.402823466e38f;
    #pragma unroll 8
    for (int c = 0; c < 80; c++) {
        float x = __ldg(q + (cb + c) * HW);
        mx = fmaxf(mx, x);
    }

    // ---- pass 2: e_c = exp(x_c - mx) ----
    float e[80];
    #pragma unroll
    for (int c = 0; c < 80; c++) {
        float x = __ldg(q + (cb + c) * HW);
        e[c] = expf(x - mx);
    }

    // ---- XLA-style warp-tree sum ----
    float t0[16], t1[16], t2[8];
    #pragma unroll
    for (int t = 0; t < 16; t++) t0[t] = e[t]      + e[t + 16];   // w0 off16
    #pragma unroll
    for (int t = 0; t < 16; t++) t1[t] = e[32 + t] + e[48 + t];   // w1 off16
    #pragma unroll
    for (int t = 0; t < 8;  t++) t0[t] = t0[t] + t0[t + 8];
    #pragma unroll
    for (int t = 0; t < 8;  t++) t1[t] = t1[t] + t1[t + 8];
    #pragma unroll
    for (int t = 0; t < 8;  t++) t2[t] = e[64 + t] + e[72 + t];   // w2 (16 live lanes) off8
    #pragma unroll
    for (int t = 0; t < 4;  t++) { t0[t] += t0[t + 4]; t1[t] += t1[t + 4]; t2[t] += t2[t + 4]; }
    #pragma unroll
    for (int t = 0; t < 2;  t++) { t0[t] += t0[t + 2]; t1[t] += t1[t + 2]; t2[t] += t2[t + 2]; }
    float w0 = t0[0] + t0[1];
    float w1 = t1[0] + t1[1];
    float w2 = t2[0] + t2[1];
    float sum = (w0 + w2) + w1;   // cross-warp tree with partials at lanes 0,1,2

    // ---- sigmoid(obj), IEEE ops ----
    float sig = __fdiv_rn(1.0f, 1.0f + expf(-obj));

    // ---- per-class score, max + first-occurrence argmax ----
    float sc = -3.402823466e38f; int am = 0;
    #pragma unroll
    for (int c = 0; c < 80; c++) {
        float s = sig * __fdiv_rn(e[c], sum);
        if (s > sc) { sc = s; am = c; }
    }

    // ---- box decode (value-tolerance path) ----
    int rb = 243 + a * 4;
    float tx = __ldg(q + rb * HW);
    float ty = __ldg(q + (rb + 1) * HW);
    float tw = __ldg(q + (rb + 2) * HW);
    float th = __ldg(q + (rb + 3) * HW);
    float cx = (__fdiv_rn(1.0f, 1.0f + expf(-tx)) + (float)ww) * stride;
    float cy = (__fdiv_rn(1.0f, 1.0f + expf(-ty)) + (float)hh) * stride;
    float aw = __ldg(anch + lvl * 6 + a * 2 + 0);
    float ah = __ldg(anch + lvl * 6 + a * 2 + 1);
    float bw = expf(tw) * aw;
    float bh = expf(th) * ah;
    float x1 = fminf(fmaxf(__fdiv_rn(cx - 0.5f * bw, 640.f), 0.f), 1.f);
    float y1 = fminf(fmaxf(__fdiv_rn(cy - 0.5f * bh, 640.f), 0.f), 1.f);
    float x2 = fminf(fmaxf(__fdiv_rn(cx + 0.5f * bw, 640.f), 0.f), 1.f);
    float y2 = fminf(fmaxf(__fdiv_rn(cy + 0.5f * bh, 640.f), 0.f), 1.f);

    g_box[idx]  = make_float4(x1, y1, x2, y2);
    float msc   = (sc >= 0.001f) ? sc : -1.0f;
    g_score[idx] = msc;
    g_cls[idx]   = am;
    atomicAdd(&g_hist[ord32(msc) >> 19], 1u);   // 13-bit bins
}

// ---------------- K2: find threshold bin (suffix count crosses TOPK) ----------------
__global__ void k_thresh() {
    __shared__ unsigned seg[256];
    int t = threadIdx.x;
    unsigned s = 0;
    for (int b = t * 32; b < t * 32 + 32; b++) s += g_hist[b];
    seg[t] = s;
    __syncthreads();
    if (t == 0) {
        unsigned cum = 0;
        int bstar = 0;
        for (int sg = 255; sg >= 0; sg--) {
            if (cum + seg[sg] >= TOPK) {
                for (int b = sg * 32 + 31; b >= sg * 32; b--) {
                    cum += g_hist[b];
                    if (cum >= TOPK) { bstar = b; break; }
                }
                break;
            }
            cum += seg[sg];
        }
        g_binThresh = bstar;
    }
}

// ---------------- K3: compact candidate keys ----------------
__global__ void k_compact() {
    int idx = blockIdx.x * blockDim.x + threadIdx.x;
    if (idx >= N_PRED) return;
    unsigned u = ord32(g_score[idx]);
    if ((int)(u >> 19) >= g_binThresh) {
        int slot = atomicAdd(&g_cnt, 1);
        if (slot < CAND_CAP)
            g_cand[slot] = ((unsigned long long)u << 32) | (unsigned)(~(unsigned)idx);
    }
}

// ---------------- K4: single-block bitonic sort (descending) + gather ----------------
__global__ void k_sort(float* __restrict__ out) {
    extern __shared__ unsigned long long sk[];
    int tid = threadIdx.x;
    int M = g_cnt; if (M > CAND_CAP) M = CAND_CAP;
    for (int t = tid; t < CAND_CAP; t += blockDim.x)
        sk[t] = (t < M) ? g_cand[t] : 0ull;
    __syncthreads();

    for (int k = 2; k <= CAND_CAP; k <<= 1) {
        for (int j = k >> 1; j > 0; j >>= 1) {
            for (int t = tid; t < CAND_CAP / 2; t += blockDim.x) {
                int i = ((t & ~(j - 1)) << 1) | (t & (j - 1));
                int p = i | j;
                unsigned long long a = sk[i], b = sk[p];
                if ((a < b) == ((i & k) == 0)) { sk[i] = b; sk[p] = a; }
            }
            __syncthreads();
        }
    }

    for (int t = tid; t < TOPK; t += blockDim.x) {
        unsigned long long key = sk[t];
        int idx = (int)(~(unsigned)(key & 0xFFFFFFFFull));
        float  sc = g_score[idx];
        float4 bx = g_box[idx];
        int    cl = g_cls[idx];
        out[t * 4 + 0] = bx.x; out[t * 4 + 1] = bx.y;
        out[t * 4 + 2] = bx.z; out[t * 4 + 3] = bx.w;
        out[16384 + t] = sc;
        out[20480 + t] = (float)cl;
        g_topbox[t] = bx;
        g_topcls[t] = cl;
        unsigned vb = __ballot_sync(0xFFFFFFFFu, sc >= 0.001f);
        if ((tid & 31) == 0) g_validw[t >> 5] = vb;
    }
}

// ---------------- K5: suppression bitmask (j suppresses i: j<i, same cls, IoU>0.6) ----
__global__ void k_mask() {
    __shared__ float4 sbi[32];
    __shared__ int    sci[32];
    __shared__ float  sai[32];
    int w = blockIdx.x;                                   // word index: i in [32w, 32w+32)
    int j = blockIdx.y * blockDim.x + threadIdx.x;        // row
    if (threadIdx.x < 32) {
        int i = w * 32 + threadIdx.x;
        float4 b = g_topbox[i];
        sbi[threadIdx.x] = b;
        sci[threadIdx.x] = g_topcls[i];
        sai[threadIdx.x] = (b.z - b.x) * (b.w - b.y);
    }
    __syncthreads();
    float4 bj = g_topbox[j];
    int    cj = g_topcls[j];
    float  aj = (bj.z - bj.x) * (bj.w - bj.y);
    unsigned m = 0;
    #pragma unroll
    for (int k = 0; k < 32; k++) {
        int i = w * 32 + k;
        if (i > j && sci[k] == cj) {
            float4 bi = sbi[k];
            float xx1 = fmaxf(bj.x, bi.x);
            float yy1 = fmaxf(bj.y, bi.y);
            float xx2 = fminf(bj.z, bi.z);
            float yy2 = fminf(bj.w, bi.w);
            float ww_ = fmaxf(1e-28f, xx2 - xx1);
            float hh_ = fmaxf(1e-28f, yy2 - yy1);
            float inter = ww_ * hh_;
            float iou = inter / (aj + sai[k] - inter + 1e-14f);
            if (iou > 0.6f) m |= 1u << k;
        }
    }
    g_mask[j * NWORD + w] = m;
}

// ---------------- K6: greedy NMS scan, 32 detections per step ----------------
__global__ void k_scan(float* __restrict__ out) {
    __shared__ unsigned sm_bc;
    __shared__ unsigned sm_m[32];
    __shared__ unsigned sm_keep[NWORD];
    int tid = threadIdx.x;
    unsigned accw = 0;                      // thread t owns removed-word t (4096 bits total)

    for (int c = 0; c < NWORD; c++) {
        if (tid == c) sm_bc = accw;                                   // expose acc word c
        if (tid < 32) sm_m[tid] = g_mask[(c * 32 + tid) * NWORD + c]; // intra-chunk words
        __syncthreads();
        if (tid == 0) {
            unsigned alive = g_validw[c] & ~sm_bc;
            #pragma unroll
            for (int k = 0; k < 32; k++)
                if ((alive >> k) & 1u) alive &= ~sm_m[k];   // kept k suppresses later in-chunk
            sm_keep[c] = alive;
        }
        __syncthreads();
        unsigned kw = sm_keep[c];
        #pragma unroll 4
        for (int k = 0; k < 32; k++)
            if ((kw >> k) & 1u) accw |= g_mask[(c * 32 + k) * NWORD + tid];
    }
    __syncthreads();
    for (int i = tid; i < TOPK; i += 128)
        out[24576 + i] = ((sm_keep[i >> 5] >> (i & 31)) & 1u) ? 1.0f : 0.0f;
}

// ---------------- launch ----------------
extern "C" void kernel_launch(void* const* d_in, const int* in_sizes, int n_in,
                              void* d_out, int out_size) {
    // identify inputs by element count (robust to metadata ordering)
    const float *ps = nullptr, *pm = nullptr, *pl = nullptr, *anch = nullptr;
    for (int i = 0; i < n_in; i++) {
        int s = in_sizes[i];
        if      (s == 255 * 80 * 80) ps   = (const float*)d_in[i];
        else if (s == 255 * 40 * 40) pm   = (const float*)d_in[i];
        else if (s == 255 * 20 * 20) pl   = (const float*)d_in[i];
        else if (s == 18)            anch = (const float*)d_in[i];
    }
    float* out = (float*)d_out;
    (void)out_size;

    cudaFuncSetAttribute(k_sort, cudaFuncAttributeMaxDynamicSharedMemorySize, 65536);

    k_init   <<<(NBIN + 255) / 256, 256>>>();
    k_decode <<<(N_PRED + 127) / 128, 128>>>(ps, pm, pl, anch);
    k_thresh <<<1, 256>>>();
    k_compact<<<(N_PRED + 255) / 256, 256>>>();
    k_sort   <<<1, 1024, 65536>>>(out);
    k_mask   <<<dim3(NWORD, 32), 128>>>();
    k_scan   <<<1, 128>>>(out);
}

// round 11
// speedup vs baseline: 2.4936x; 2.4936x over previous
#include <cuda_runtime.h>
#include <cstdint>

#define N_PRED   25200
#define N_S      19200
#define N_SM     24000   // s + m
#define TOPK     4096
#define NBIN     8192
#define CAND_CAP 8192
#define NWORD    128     // TOPK / 32

// ---------------- scratch (static __device__, no allocations) ----------------
__device__ float              g_score[N_PRED];
__device__ int                g_cls[N_PRED];
__device__ float4             g_box[N_PRED];
__device__ unsigned           g_hist[NBIN];
__device__ int                g_cnt;
__device__ int                g_binThresh;
__device__ unsigned long long g_cand[CAND_CAP];
__device__ float4             g_topbox[TOPK];
__device__ int                g_topcls[TOPK];
__device__ unsigned           g_validw[NWORD];
__device__ unsigned           g_mask[TOPK * NWORD];   // 2 MB suppression bitmask

__device__ __forceinline__ unsigned ord32(float f) {
    unsigned u = __float_as_uint(f);
    return (u & 0x80000000u) ? ~u : (u | 0x80000000u);
}

// ---------------- K0: clear counters ----------------
__global__ void k_init() {
    int t = blockIdx.x * blockDim.x + threadIdx.x;
    if (t < NBIN) g_hist[t] = 0u;
    if (t == 0)   g_cnt = 0;
}

// ---------------- K1: decode all predictions ----------------
// Score replicates XLA:GPU fused softmax bit-for-bit (CONFIRMED in R5: rel_err 7e-8):
//   mx, e_c = expf(x_c - mx), sum = shuffle-tree (w0 + w2) + w1,
//   s_c = sig * (e_c / sum), strict-> first-occurrence argmax.
// DO NOT change this arithmetic — it is load-bearing for correctness.
__global__ void k_decode(const float* __restrict__ ps, const float* __restrict__ pm,
                         const float* __restrict__ pl, const float* __restrict__ anch) {
    int idx = blockIdx.x * blockDim.x + threadIdx.x;
    if (idx >= N_PRED) return;

    const float* p; int HW, W, lvl, li; float stride;
    if (idx < N_S)       { p = ps; HW = 6400; W = 80; stride = 8.f;  lvl = 0; li = idx; }
    else if (idx < N_SM) { p = pm; HW = 1600; W = 40; stride = 16.f; lvl = 1; li = idx - N_S; }
    else                 { p = pl; HW = 400;  W = 20; stride = 32.f; lvl = 2; li = idx - N_SM; }

    int pos = li / 3, a = li - pos * 3;
    int hh = pos / W, ww = pos - hh * W;
    const float* q = p + pos;

    float obj = __ldg(q + a * HW);

    // ---- pass 1: row max (order-independent) ----
    int cb = 3 + a * 80;
    float mx = -3.402823466e38f;
    #pragma unroll 8
    for (int c = 0; c < 80; c++) {
        float x = __ldg(q + (cb + c) * HW);
        mx = fmaxf(mx, x);
    }

    // ---- pass 2: e_c = exp(x_c - mx) ----
    float e[80];
    #pragma unroll
    for (int c = 0; c < 80; c++) {
        float x = __ldg(q + (cb + c) * HW);
        e[c] = expf(x - mx);
    }

    // ---- XLA-style warp-tree sum ----
    float t0[16], t1[16], t2[8];
    #pragma unroll
    for (int t = 0; t < 16; t++) t0[t] = e[t]      + e[t + 16];   // w0 off16
    #pragma unroll
    for (int t = 0; t < 16; t++) t1[t] = e[32 + t] + e[48 + t];   // w1 off16
    #pragma unroll
    for (int t = 0; t < 8;  t++) t0[t] = t0[t] + t0[t + 8];
    #pragma unroll
    for (int t = 0; t < 8;  t++) t1[t] = t1[t] + t1[t + 8];
    #pragma unroll
    for (int t = 0; t < 8;  t++) t2[t] = e[64 + t] + e[72 + t];   // w2 (16 live lanes) off8
    #pragma unroll
    for (int t = 0; t < 4;  t++) { t0[t] += t0[t + 4]; t1[t] += t1[t + 4]; t2[t] += t2[t + 4]; }
    #pragma unroll
    for (int t = 0; t < 2;  t++) { t0[t] += t0[t + 2]; t1[t] += t1[t + 2]; t2[t] += t2[t + 2]; }
    float w0 = t0[0] + t0[1];
    float w1 = t1[0] + t1[1];
    float w2 = t2[0] + t2[1];
    float sum = (w0 + w2) + w1;   // cross-warp tree with partials at lanes 0,1,2

    // ---- sigmoid(obj), IEEE ops ----
    float sig = __fdiv_rn(1.0f, 1.0f + expf(-obj));

    // ---- per-class score, max + first-occurrence argmax ----
    float sc = -3.402823466e38f; int am = 0;
    #pragma unroll
    for (int c = 0; c < 80; c++) {
        float s = sig * __fdiv_rn(e[c], sum);
        if (s > sc) { sc = s; am = c; }
    }

    // ---- box decode (value-tolerance path) ----
    int rb = 243 + a * 4;
    float tx = __ldg(q + rb * HW);
    float ty = __ldg(q + (rb + 1) * HW);
    float tw = __ldg(q + (rb + 2) * HW);
    float th = __ldg(q + (rb + 3) * HW);
    float cx = (__fdiv_rn(1.0f, 1.0f + expf(-tx)) + (float)ww) * stride;
    float cy = (__fdiv_rn(1.0f, 1.0f + expf(-ty)) + (float)hh) * stride;
    float aw = __ldg(anch + lvl * 6 + a * 2 + 0);
    float ah = __ldg(anch + lvl * 6 + a * 2 + 1);
    float bw = expf(tw) * aw;
    float bh = expf(th) * ah;
    float x1 = fminf(fmaxf(__fdiv_rn(cx - 0.5f * bw, 640.f), 0.f), 1.f);
    float y1 = fminf(fmaxf(__fdiv_rn(cy - 0.5f * bh, 640.f), 0.f), 1.f);
    float x2 = fminf(fmaxf(__fdiv_rn(cx + 0.5f * bw, 640.f), 0.f), 1.f);
    float y2 = fminf(fmaxf(__fdiv_rn(cy + 0.5f * bh, 640.f), 0.f), 1.f);

    g_box[idx]  = make_float4(x1, y1, x2, y2);
    float msc   = (sc >= 0.001f) ? sc : -1.0f;
    g_score[idx] = msc;
    g_cls[idx]   = am;
    atomicAdd(&g_hist[ord32(msc) >> 19], 1u);   // 13-bit bins
}

// ---------------- K2: find threshold bin (suffix count crosses TOPK) ----------------
__global__ void k_thresh() {
    __shared__ unsigned seg[256];
    int t = threadIdx.x;
    unsigned s = 0;
    for (int b = t * 32; b < t * 32 + 32; b++) s += g_hist[b];
    seg[t] = s;
    __syncthreads();
    if (t == 0) {
        unsigned cum = 0;
        int bstar = 0;
        for (int sg = 255; sg >= 0; sg--) {
            if (cum + seg[sg] >= TOPK) {
                for (int b = sg * 32 + 31; b >= sg * 32; b--) {
                    cum += g_hist[b];
                    if (cum >= TOPK) { bstar = b; break; }
                }
                break;
            }
            cum += seg[sg];
        }
        g_binThresh = bstar;
    }
}

// ---------------- K3: compact candidate keys ----------------
__global__ void k_compact() {
    int idx = blockIdx.x * blockDim.x + threadIdx.x;
    if (idx >= N_PRED) return;
    unsigned u = ord32(g_score[idx]);
    if ((int)(u >> 19) >= g_binThresh) {
        int slot = atomicAdd(&g_cnt, 1);
        if (slot < CAND_CAP)
            g_cand[slot] = ((unsigned long long)u << 32) | (unsigned)(~(unsigned)idx);
    }
}

// ---------------- K4: single-block bitonic sort (descending) + gather ----------------
__global__ void k_sort(float* __restrict__ out) {
    extern __shared__ unsigned long long sk[];
    int tid = threadIdx.x;
    int M = g_cnt; if (M > CAND_CAP) M = CAND_CAP;
    for (int t = tid; t < CAND_CAP; t += blockDim.x)
        sk[t] = (t < M) ? g_cand[t] : 0ull;
    __syncthreads();

    for (int k = 2; k <= CAND_CAP; k <<= 1) {
        for (int j = k >> 1; j > 0; j >>= 1) {
            for (int t = tid; t < CAND_CAP / 2; t += blockDim.x) {
                int i = ((t & ~(j - 1)) << 1) | (t & (j - 1));
                int p = i | j;
                unsigned long long a = sk[i], b = sk[p];
                if ((a < b) == ((i & k) == 0)) { sk[i] = b; sk[p] = a; }
            }
            __syncthreads();
        }
    }

    for (int t = tid; t < TOPK; t += blockDim.x) {
        unsigned long long key = sk[t];
        int idx = (int)(~(unsigned)(key & 0xFFFFFFFFull));
        float  sc = g_score[idx];
        float4 bx = g_box[idx];
        int    cl = g_cls[idx];
        out[t * 4 + 0] = bx.x; out[t * 4 + 1] = bx.y;
        out[t * 4 + 2] = bx.z; out[t * 4 + 3] = bx.w;
        out[16384 + t] = sc;
        out[20480 + t] = (float)cl;
        g_topbox[t] = bx;
        g_topcls[t] = cl;
        unsigned vb = __ballot_sync(0xFFFFFFFFu, sc >= 0.001f);
        if ((tid & 31) == 0) g_validw[t >> 5] = vb;
    }
}

// ---------------- K5: suppression bitmask (j suppresses i: j<i, same cls, IoU>0.6) ----
__global__ void k_mask() {
    __shared__ float4 sbi[32];
    __shared__ int    sci[32];
    __shared__ float  sai[32];
    int w = blockIdx.x;                                   // word index: i in [32w, 32w+32)
    int j = blockIdx.y * blockDim.x + threadIdx.x;        // row
    if (threadIdx.x < 32) {
        int i = w * 32 + threadIdx.x;
        float4 b = g_topbox[i];
        sbi[threadIdx.x] = b;
        sci[threadIdx.x] = g_topcls[i];
        sai[threadIdx.x] = (b.z - b.x) * (b.w - b.y);
    }
    __syncthreads();
    float4 bj = g_topbox[j];
    int    cj = g_topcls[j];
    float  aj = (bj.z - bj.x) * (bj.w - bj.y);
    unsigned m = 0;
    #pragma unroll
    for (int k = 0; k < 32; k++) {
        int i = w * 32 + k;
        if (i > j && sci[k] == cj) {
            float4 bi = sbi[k];
            float xx1 = fmaxf(bj.x, bi.x);
            float yy1 = fmaxf(bj.y, bi.y);
            float xx2 = fminf(bj.z, bi.z);
            float yy2 = fminf(bj.w, bi.w);
            float ww_ = fmaxf(1e-28f, xx2 - xx1);
            float hh_ = fmaxf(1e-28f, yy2 - yy1);
            float inter = ww_ * hh_;
            float iou = inter / (aj + sai[k] - inter + 1e-14f);
            if (iou > 0.6f) m |= 1u << k;
        }
    }
    g_mask[j * NWORD + w] = m;
}

// ---------------- K6: greedy NMS scan — register-pipelined, 1 sync/chunk ----------------
// Thread t owns removed-bitmask word t. Chunk c's 32 mask rows (word t each) are
// prefetched into registers TWO chunks ahead (ping-pong bufA/bufB), so the demand
// latency that dominated R5 (~440us of serialized L2 misses) is fully hidden.
// The greedy resolve for chunk c runs on thread c, whose registers already hold the
// chunk's diagonal words — no shared staging, one barrier per chunk.
__global__ void __launch_bounds__(128, 1) k_scan(float* __restrict__ out) {
    __shared__ unsigned sm_keep[NWORD];
    int tid = threadIdx.x;
    unsigned accw = 0;                       // removed-word owned by this thread
    unsigned myvalid = g_validw[tid];        // valid word tid (used when tid == c)

    unsigned bufA[32], bufB[32];
    #pragma unroll
    for (int k = 0; k < 32; k++) bufA[k] = g_mask[(0 * 32 + k) * NWORD + tid];
    #pragma unroll
    for (int k = 0; k < 32; k++) bufB[k] = g_mask[(1 * 32 + k) * NWORD + tid];

    for (int c = 0; c < NWORD; c += 2) {
        // -------- chunk c (bufA) --------
        if (tid == c) {
            unsigned alive = myvalid & ~accw;
            #pragma unroll
            for (int k = 0; k < 32; k++)
                if ((alive >> k) & 1u) alive &= ~bufA[k];   // kept k kills later in-chunk
            sm_keep[c] = alive;
        }
        __syncthreads();
        {
            unsigned kw = sm_keep[c];
            #pragma unroll
            for (int k = 0; k < 32; k++)
                if ((kw >> k) & 1u) accw |= bufA[k];
        }
        if (c + 2 < NWORD) {
            #pragma unroll
            for (int k = 0; k < 32; k++)
                bufA[k] = g_mask[((c + 2) * 32 + k) * NWORD + tid];  // in flight ~2 chunks
        }

        // -------- chunk c+1 (bufB) --------
        if (tid == c + 1) {
            unsigned alive = myvalid & ~accw;
            #pragma unroll
            for (int k = 0; k < 32; k++)
                if ((alive >> k) & 1u) alive &= ~bufB[k];
            sm_keep[c + 1] = alive;
        }
        __syncthreads();
        {
            unsigned kw = sm_keep[c + 1];
            #pragma unroll
            for (int k = 0; k < 32; k++)
                if ((kw >> k) & 1u) accw |= bufB[k];
        }
        if (c + 3 < NWORD) {
            #pragma unroll
            for (int k = 0; k < 32; k++)
                bufB[k] = g_mask[((c + 3) * 32 + k) * NWORD + tid];
        }
    }
    __syncthreads();
    for (int i = tid; i < TOPK; i += 128)
        out[24576 + i] = ((sm_keep[i >> 5] >> (i & 31)) & 1u) ? 1.0f : 0.0f;
}

// ---------------- launch ----------------
extern "C" void kernel_launch(void* const* d_in, const int* in_sizes, int n_in,
                              void* d_out, int out_size) {
    // identify inputs by element count (robust to metadata ordering)
    const float *ps = nullptr, *pm = nullptr, *pl = nullptr, *anch = nullptr;
    for (int i = 0; i < n_in; i++) {
        int s = in_sizes[i];
        if      (s == 255 * 80 * 80) ps   = (const float*)d_in[i];
        else if (s == 255 * 40 * 40) pm   = (const float*)d_in[i];
        else if (s == 255 * 20 * 20) pl   = (const float*)d_in[i];
        else if (s == 18)            anch = (const float*)d_in[i];
    }
    float* out = (float*)d_out;
    (void)out_size;

    cudaFuncSetAttribute(k_sort, cudaFuncAttributeMaxDynamicSharedMemorySize, 65536);

    k_init   <<<(NBIN + 255) / 256, 256>>>();
    k_decode <<<(N_PRED + 127) / 128, 128>>>(ps, pm, pl, anch);
    k_thresh <<<1, 256>>>();
    k_compact<<<(N_PRED + 255) / 256, 256>>>();
    k_sort   <<<1, 1024, 65536>>>(out);
    k_mask   <<<dim3(NWORD, 32), 128>>>();
    k_scan   <<<1, 128>>>(out);
}